// round 8
// baseline (speedup 1.0000x reference)
#include <cuda_runtime.h>
#include <cuda_fp16.h>
#include <cstdint>

// Problem constants
#define BN   8192      // batch
#define FK   128       // feature dim (GEMM K)
#define DD   10000     // hypervector dim
#define CC   100       // classes
#define HV_W 320       // padded u32 words per hv row (layout constant)

#define MT   64        // m tiles (8192/128)
#define NT   79        // n tiles (10112 padded / 128)
#define NCHK 80        // proto uint4 chunks
#define TILE_U4 2048   // uint4 per 128x128 fp16 tile (32 KB)

#define NG   16        // n-groups for fused gemm (tiles per group: 5, last 4)
#define DOTC 104       // pdot row stride (100 dots + rowpop @100 + pad)
#define SLICE (128 * DOTC)

// fused prep grid partition
#define PA_BLOCKS 2048                      // prep_a: 8192*64 threads
#define PB_BLOCKS 2528                      // prep_b: 64*NT*128 threads
#define PREP_BLOCKS (PA_BLOCKS + PB_BLOCKS + CC)

// ---------------- scratch (device globals; no allocation allowed) ----------------
__device__ uint4 g_proto[NCHK * CC];          // packed prototypes [chunk][class]
__device__ int   g_protopop[CC];              // per-class popcount
__device__ uint4 g_Abf[2 * MT * TILE_U4];     // feat 2-split fp16 planes (4 MB)
__device__ uint4 g_Bbf[NT * TILE_U4];         // R fp16, tile-image layout (2.6 MB)
__device__ int   g_pdot[MT * NG * SLICE];     // partial dots + rowpop (54.5 MB)

// ============================ helpers ==============================
__device__ __forceinline__ uint32_t smem_u32(const void* p) {
    uint32_t a;
    asm("{ .reg .u64 t; cvta.to.shared.u64 t, %1; cvt.u32.u64 %0, t; }" : "=r"(a) : "l"(p));
    return a;
}

#define CP_ASYNC16(dst, src) \
    asm volatile("cp.async.cg.shared.global [%0], [%1], 16;" :: "r"(dst), "l"(src) : "memory")
#define CP_COMMIT() asm volatile("cp.async.commit_group;" ::: "memory")
template <int N>
__device__ __forceinline__ void cp_wait() {
    asm volatile("cp.async.wait_group %0;" :: "n"(N) : "memory");
}

__device__ __forceinline__ void ldsm4(uint32_t addr, uint32_t& r0, uint32_t& r1,
                                      uint32_t& r2, uint32_t& r3) {
    asm volatile("ldmatrix.sync.aligned.m8n8.x4.shared.b16 {%0,%1,%2,%3}, [%4];"
                 : "=r"(r0), "=r"(r1), "=r"(r2), "=r"(r3) : "r"(addr));
}

__device__ __forceinline__ void mma16816(float* c, uint32_t a0, uint32_t a1,
                                         uint32_t a2, uint32_t a3,
                                         uint32_t b0, uint32_t b1) {
    asm volatile(
        "mma.sync.aligned.m16n8k16.row.col.f32.f16.f16.f32 "
        "{%0,%1,%2,%3}, {%4,%5,%6,%7}, {%8,%9}, {%0,%1,%2,%3};"
        : "+f"(c[0]), "+f"(c[1]), "+f"(c[2]), "+f"(c[3])
        : "r"(a0), "r"(a1), "r"(a2), "r"(a3), "r"(b0), "r"(b1));
}

// blocked-atom SW128 byte offset within a 128x128 fp16 tile (atom = 8 rows x 64 halves)
__device__ __forceinline__ uint32_t tile_off(int row, int col) {
    const uint32_t b = (uint32_t)(((row >> 3) + (col >> 6) * 16) * 1024
                                  + (row & 7) * 128 + (col & 63) * 2);
    return b ^ ((b >> 3) & 0x70);
}

__device__ __forceinline__ int popc4(uint4 a, uint4 b) {
    return __popc(a.x & b.x) + __popc(a.y & b.y) + __popc(a.z & b.z) + __popc(a.w & b.w);
}

// =================================================================================
// Fused prep kernel (unchanged behavior): A 2-way fp16 split, B fp16 tiles,
// prototype bit-pack + popcount with dtype auto-detect.
// =================================================================================
__global__ void __launch_bounds__(256) prep_fused_kernel(const float* __restrict__ feat,
                                                         const float* __restrict__ R,
                                                         const void*  __restrict__ proto_raw)
{
    const int bx = blockIdx.x;

    if (bx < PA_BLOCKS) {
        const int idx = bx * 256 + threadIdx.x;     // 8192*64
        const int b   = idx >> 6;
        const int kp  = idx & 63;
        const int t   = b >> 7, m = b & 127, k = kp * 2;

        const float2 x = *(const float2*)(feat + b * FK + k);

        unsigned w[2];
        {
            float v0 = x.x, v1 = x.y;
            #pragma unroll
            for (int s = 0; s < 2; s++) {
                const __half h0 = __float2half(v0);
                const __half h1 = __float2half(v1);
                w[s] = ((unsigned)__half_as_ushort(h1) << 16) | __half_as_ushort(h0);
                v0 -= __half2float(h0);
                v1 -= __half2float(h1);
            }
        }

        const uint32_t off = tile_off(m, k) >> 2;
        unsigned* base = (unsigned*)g_Abf;
        #pragma unroll
        for (int s = 0; s < 2; s++)
            base[(s * MT + t) * (TILE_U4 * 4) + off] = w[s];
        return;
    }

    if (bx < PA_BLOCKS + PB_BLOCKS) {
        const int idx = (bx - PA_BLOCKS) * 256 + threadIdx.x;   // 64 * NT*128 exactly
        const int kp = idx / (NT * 128);
        const int d  = idx - kp * (NT * 128);
        const int t  = d >> 7, n = d & 127, k = kp * 2;

        float v0 = 0.0f, v1 = 0.0f;
        if (d < DD) {
            v0 = R[k * DD + d];
            v1 = R[(k + 1) * DD + d];
        }
        const __half h0 = __float2half(v0);   // +/-1 exact
        const __half h1 = __float2half(v1);
        const unsigned w = ((unsigned)__half_as_ushort(h1) << 16) | __half_as_ushort(h0);

        ((unsigned*)g_Bbf)[t * (TILE_U4 * 4) + (tile_off(n, k) >> 2)] = w;
        return;
    }

    // ---------------- pack prototypes ----------------
    const int c   = bx - (PA_BLOCKS + PB_BLOCKS);
    const int tid = threadIdx.x;

    __shared__ int s_f32bad, s_i32bad;
    if (tid == 0) { s_f32bad = 0; s_i32bad = 0; }
    __syncthreads();
    {
        const unsigned v = ((const unsigned*)proto_raw)[tid];
        if (v != 0u && v != 0x3F800000u) atomicOr(&s_f32bad, 1);
        if (v > 1u)                      atomicOr(&s_i32bad, 1);
    }
    __syncthreads();
    const int mode = (!s_f32bad) ? 2 : ((!s_i32bad) ? 1 : 0);   // 2=f32, 1=i32, 0=u8

    const unsigned char* p8  = (const unsigned char*)proto_raw;
    const int*           p32 = (const int*)proto_raw;
    const float*         pf  = (const float*)proto_raw;

    int sum = 0;
    for (int w = tid; w < HV_W; w += 256) {
        unsigned word = 0;
        if (w < 313) {
            const int dbase = w * 32;
            #pragma unroll 8
            for (int j = 0; j < 32; j++) {
                const int d = dbase + j;
                if (d < DD) {
                    bool bit;
                    if (mode == 2)      bit = (pf[c * DD + d] != 0.0f);
                    else if (mode == 1) bit = (p32[c * DD + d] != 0);
                    else                bit = (p8[c * DD + d] != 0);
                    if (bit) word |= (1u << j);
                }
            }
        }
        sum += __popc(word);
        ((unsigned*)g_proto)[((w >> 2) * CC + c) * 4 + (w & 3)] = word;
    }

    __shared__ int red[256];
    red[tid] = sum;
    __syncthreads();
    #pragma unroll
    for (int s = 128; s > 0; s >>= 1) {
        if (tid < s) red[tid] += red[tid + s];
        __syncthreads();
    }
    if (tid == 0) g_protopop[c] = red[0];
}

// =================================================================================
// Fused GEMM + dot kernel.
// Grid (NG=16 groups, MT=64). CTA: m-tile mt, n-tiles nt0..nt0+cnt.
// A (both fp16 planes, 64 KB) resident across n-tiles; B + proto double-buffered.
// Per tile: MMA -> pack bits -> per-thread register dot accumulate (25 classes/thread).
// End: write [128][100]+rowpop slice to g_pdot (atomic-free).
// =================================================================================
#define SMO_A0   0
#define SMO_A1   32768
#define SMO_B0   65536
#define SMO_B1   98304
#define SMO_WRD  131072        // 2048 B: words [128][4]
#define SMO_P0   133120        // 1600 B: proto chunk buf 0
#define SMO_P1   134720        // 1600 B: proto chunk buf 1
#define SM_TOT   136320

__global__ void __launch_bounds__(512, 1) gemm_kernel()
{
    extern __shared__ char sm[];
    const uint32_t smem_base = smem_u32(sm);
    const int tid  = threadIdx.x;
    const int lane = tid & 31, wid = tid >> 5;
    const int grp = blockIdx.x, mt = blockIdx.y;
    const int nt0 = grp * 5;
    const int cnt = (79 - nt0 < 5) ? (79 - nt0) : 5;   // 5 tiles, last group 4

    // ---- prologue async copies ----
    {
        const uint4* srcA0 = g_Abf + (0 * MT + mt) * TILE_U4;
        const uint4* srcA1 = g_Abf + (1 * MT + mt) * TILE_U4;
        #pragma unroll
        for (int i = 0; i < 4; i++) {
            const int j = tid + i * 512;
            CP_ASYNC16(smem_base + SMO_A0 + j * 16, (const void*)(srcA0 + j));
            CP_ASYNC16(smem_base + SMO_A1 + j * 16, (const void*)(srcA1 + j));
        }
        const uint4* srcB0 = g_Bbf + (nt0 + 0) * TILE_U4;
        #pragma unroll
        for (int i = 0; i < 4; i++) {
            const int j = tid + i * 512;
            CP_ASYNC16(smem_base + SMO_B0 + j * 16, (const void*)(srcB0 + j));
        }
        if (tid < CC)
            CP_ASYNC16(smem_base + SMO_P0 + tid * 16, (const void*)(g_proto + (nt0 + 0) * CC + tid));
        CP_COMMIT();   // G0: A + B0 + P0

        const uint4* srcB1 = g_Bbf + (nt0 + 1) * TILE_U4;
        #pragma unroll
        for (int i = 0; i < 4; i++) {
            const int j = tid + i * 512;
            CP_ASYNC16(smem_base + SMO_B1 + j * 16, (const void*)(srcB1 + j));
        }
        if (tid < CC)
            CP_ASYNC16(smem_base + SMO_P1 + tid * 16, (const void*)(g_proto + (nt0 + 1) * CC + tid));
        CP_COMMIT();   // G1: B1 + P1
    }

    // warp tiles: 16 warps, 32m x 32n
    const int wm = (wid & 3) * 32;
    const int wn = (wid >> 2) * 32;

    uint32_t rbA[2], sxA[2];
    #pragma unroll
    for (int mf = 0; mf < 2; mf++) {
        const int r = wm + mf * 16 + (lane & 15);
        rbA[mf] = (uint32_t)((r >> 3) * 1024 + (r & 7) * 128);
        sxA[mf] = (uint32_t)((r & 7) << 4);
    }
    const uint32_t colselA = (lane & 16) >> 1;   // 0 or 8

    uint32_t rbB[2], sxB[2];
    #pragma unroll
    for (int p = 0; p < 2; p++) {
        const int r = wn + p * 16 + (lane & 7) + ((lane & 16) >> 1);
        rbB[p] = (uint32_t)((r >> 3) * 1024 + (r & 7) * 128);
        sxB[p] = (uint32_t)((r & 7) << 4);
    }
    const uint32_t colselB = lane & 8;

    unsigned* words_s = (unsigned*)(sm + SMO_WRD);   // [128][4]

    // per-thread dot ownership: row r_ep, classes cq..cq+24
    const int r_ep = tid >> 2;
    const int cq   = (tid & 3) * 25;
    int dot_reg[25];
    #pragma unroll
    for (int i = 0; i < 25; i++) dot_reg[i] = 0;
    int rp = 0;

    for (int j = 0; j < cnt; j++) {
        cp_wait<1>();
        __syncthreads();

        float acc[2][4][4];
        #pragma unroll
        for (int mf = 0; mf < 2; mf++)
            #pragma unroll
            for (int nf = 0; nf < 4; nf++)
                #pragma unroll
                for (int i = 0; i < 4; i++) acc[mf][nf][i] = 0.0f;

        const uint32_t bBase = smem_base + ((j & 1) ? SMO_B1 : SMO_B0);

        #pragma unroll
        for (int s = 0; s < 2; s++) {
            const uint32_t aBase = smem_base + (s ? SMO_A1 : SMO_A0);
            #pragma unroll
            for (int kk = 0; kk < 8; kk++) {
                const int k0 = kk * 16;

                uint32_t a[2][4];
                {
                    const int col = k0 + (int)colselA;
                    const uint32_t chi = (col >= 64) ? 16384u : 0u;
                    const uint32_t clo = (uint32_t)((col & 63) << 1);
                    #pragma unroll
                    for (int mf = 0; mf < 2; mf++) {
                        const uint32_t addr = aBase + rbA[mf] + chi + (clo ^ sxA[mf]);
                        ldsm4(addr, a[mf][0], a[mf][1], a[mf][2], a[mf][3]);
                    }
                }

                uint32_t b[4][2];
                {
                    const int col = k0 + (int)colselB;
                    const uint32_t chi = (col >= 64) ? 16384u : 0u;
                    const uint32_t clo = (uint32_t)((col & 63) << 1);
                    #pragma unroll
                    for (int p = 0; p < 2; p++) {
                        const uint32_t addr = bBase + rbB[p] + chi + (clo ^ sxB[p]);
                        uint32_t r0, r1, r2, r3;
                        ldsm4(addr, r0, r1, r2, r3);
                        b[2 * p][0]     = r0;
                        b[2 * p][1]     = r1;
                        b[2 * p + 1][0] = r2;
                        b[2 * p + 1][1] = r3;
                    }
                }

                #pragma unroll
                for (int mf = 0; mf < 2; mf++)
                    #pragma unroll
                    for (int nf = 0; nf < 4; nf++)
                        mma16816(acc[mf][nf], a[mf][0], a[mf][1], a[mf][2], a[mf][3],
                                 b[nf][0], b[nf][1]);
            }
        }

        // ---- pack: binarize + shfl-OR; warp covers word column wn>>5 ----
        {
            const int q2 = (lane & 3) * 2;
            const int gg = lane >> 2;
            const int cw = wn >> 5;
            #pragma unroll
            for (int mf = 0; mf < 2; mf++) {
                unsigned lo = 0, hi = 0;
                #pragma unroll
                for (int nf = 0; nf < 4; nf++) {
                    lo |= (acc[mf][nf][0] > 0.0f ? 1u : 0u) << (8 * nf + q2);
                    lo |= (acc[mf][nf][1] > 0.0f ? 1u : 0u) << (8 * nf + q2 + 1);
                    hi |= (acc[mf][nf][2] > 0.0f ? 1u : 0u) << (8 * nf + q2);
                    hi |= (acc[mf][nf][3] > 0.0f ? 1u : 0u) << (8 * nf + q2 + 1);
                }
                lo |= __shfl_xor_sync(0xffffffffu, lo, 1);
                lo |= __shfl_xor_sync(0xffffffffu, lo, 2);
                hi |= __shfl_xor_sync(0xffffffffu, hi, 1);
                hi |= __shfl_xor_sync(0xffffffffu, hi, 2);
                if ((lane & 3) == 0) {
                    words_s[(wm + mf * 16 + gg) * 4 + cw]     = lo;
                    words_s[(wm + mf * 16 + gg + 8) * 4 + cw] = hi;
                }
            }
        }
        __syncthreads();   // pack visible to dot

        // ---- dot accumulate (registers) ----
        {
            const uint4 h = *(const uint4*)&words_s[r_ep * 4];
            if ((tid & 3) == 0)
                rp += __popc(h.x) + __popc(h.y) + __popc(h.z) + __popc(h.w);
            const uint4* ps = (const uint4*)(sm + ((j & 1) ? SMO_P1 : SMO_P0));
            #pragma unroll
            for (int i = 0; i < 25; i++) {
                const uint4 p = ps[cq + i];
                dot_reg[i] += popc4(p, h);
            }
        }
        __syncthreads();   // dot done before buffers refilled / words reused

        // ---- refill buf (j&1) for tile j+2; always commit (empty ok) ----
        if (j + 2 < cnt) {
            const int nt2 = nt0 + j + 2;
            const uint32_t bDst = smem_base + ((j & 1) ? SMO_B1 : SMO_B0);
            const uint4* srcB = g_Bbf + nt2 * TILE_U4;
            #pragma unroll
            for (int i = 0; i < 4; i++) {
                const int jj = tid + i * 512;
                CP_ASYNC16(bDst + jj * 16, (const void*)(srcB + jj));
            }
            if (tid < CC) {
                const uint32_t pDst = smem_base + ((j & 1) ? SMO_P1 : SMO_P0);
                CP_ASYNC16(pDst + tid * 16, (const void*)(g_proto + nt2 * CC + tid));
            }
        }
        CP_COMMIT();
    }

    // ---- write partial-dot slice ----
    int* dst = g_pdot + (mt * NG + grp) * SLICE + r_ep * DOTC;
    #pragma unroll
    for (int i = 0; i < 25; i++) dst[cq + i] = dot_reg[i];
    if ((tid & 3) == 0) dst[100] = rp;
}

// =================================================================================
// Final kernel: sum NG partial slices -> sims -> argmax -> outputs.
// Grid 64 (one per m-tile), 256 threads, dynamic smem 51.2 KB for sims.
// =================================================================================
__global__ void __launch_bounds__(256) argmax_kernel(const float* __restrict__ counts,
                                                     float* __restrict__ out_pred_f,
                                                     int*   __restrict__ out_pred_i,
                                                     float* __restrict__ out_sims)
{
    extern __shared__ float sims_s[];   // [128][100]
    __shared__ int rowpop_s[128];

    const int mt  = blockIdx.x;
    const int tid = threadIdx.x;
    const int* base = g_pdot + mt * NG * SLICE;

    for (int r = tid; r < 128; r += 256) {
        int s = 0;
        #pragma unroll
        for (int g = 0; g < NG; g++) s += base[g * SLICE + r * DOTC + 100];
        rowpop_s[r] = s;
    }
    __syncthreads();

    for (int idx = tid; idx < 128 * CC; idx += 256) {
        const int r = idx / CC;
        const int c = idx - r * CC;
        int dt = 0;
        #pragma unroll
        for (int g = 0; g < NG; g++) dt += base[g * SLICE + r * DOTC + c];
        const int ham = rowpop_s[r] + g_protopop[c] - 2 * dt;
        const float sv = (counts[c] > 0.0f) ? (1.0f - (float)ham / 10000.0f) : 0.0f;
        sims_s[r * CC + c] = sv;
        if (out_sims) out_sims[(mt * 128 + r) * CC + c] = sv;
    }
    __syncthreads();

    if (tid < 128) {
        float best = sims_s[tid * CC];
        int   bidx = 0;
        for (int c = 1; c < CC; c++) {
            const float v = sims_s[tid * CC + c];
            if (v > best) { best = v; bidx = c; }
        }
        if (out_pred_f) out_pred_f[mt * 128 + tid] = (float)bidx;
        if (out_pred_i) out_pred_i[mt * 128 + tid] = bidx;
    }
}

// =================================================================================
// Launch
// =================================================================================
extern "C" void kernel_launch(void* const* d_in, const int* in_sizes, int n_in,
                              void* d_out, int out_size)
{
    const float* feat   = (const float*)d_in[0];
    const float* R      = (const float*)d_in[1];
    const void*  proto  = d_in[2];
    const float* counts = (const float*)d_in[3];

    cudaFuncSetAttribute(gemm_kernel, cudaFuncAttributeMaxDynamicSharedMemorySize, SM_TOT);
    cudaFuncSetAttribute(argmax_kernel, cudaFuncAttributeMaxDynamicSharedMemorySize,
                         128 * CC * (int)sizeof(float));

    prep_fused_kernel<<<PREP_BLOCKS, 256>>>(feat, R, proto);
    gemm_kernel<<<dim3(NG, MT), 512, SM_TOT>>>();

    float* outf   = (float*)d_out;
    float* pred_f = nullptr;
    int*   pred_i = nullptr;
    float* sims   = nullptr;
    if (out_size >= BN + BN * CC) {
        pred_f = outf;
        sims   = outf + BN;
    } else if (out_size >= BN * CC) {
        sims = outf;
    } else {
        pred_i = (int*)d_out;
    }

    argmax_kernel<<<MT, 256, 128 * CC * sizeof(float)>>>(counts, pred_f, pred_i, sims);
}

// round 9
// speedup vs baseline: 1.3251x; 1.3251x over previous
#include <cuda_runtime.h>
#include <cuda_fp16.h>
#include <cstdint>

// Problem constants
#define BN   8192      // batch
#define FK   128       // feature dim (GEMM K)
#define DD   10000     // hypervector dim
#define CC   100       // classes
#define HV_W 320       // padded u32 words per hv row
#define NCH  80        // uint4 chunks per row (hamming)

#define MT   64        // m tiles (8192/128)
#define NT   79        // n tiles (10112 padded / 128)
#define TILE_U4 2048   // uint4 per 128x128 fp16 tile (32 KB)

#define NG   16        // n-groups for gemm (tiles per group: 5, last group 4)

// fused prep grid partition
#define PA_BLOCKS 2048                      // prep_a: 8192*64 threads
#define PB_BLOCKS 2528                      // prep_b: 64*NT*128 threads
#define PREP_BLOCKS (PA_BLOCKS + PB_BLOCKS + CC)

// ---------------- scratch (device globals; no allocation allowed) ----------------
__device__ unsigned g_hv[BN * HV_W];            // bitpacked hypervectors (~10.5 MB)
__device__ uint4    g_proto[NCH * CC];          // packed prototypes [chunk][class]
__device__ int      g_protopop[CC];             // per-class popcount
__device__ uint4    g_Abf[2 * MT * TILE_U4];    // feat 2-split fp16 planes (4 MB)
__device__ uint4    g_Bbf[NT * TILE_U4];        // R fp16, tile-image layout (2.6 MB)

// ============================ helpers ==============================
__device__ __forceinline__ uint32_t smem_u32(const void* p) {
    uint32_t a;
    asm("{ .reg .u64 t; cvta.to.shared.u64 t, %1; cvt.u32.u64 %0, t; }" : "=r"(a) : "l"(p));
    return a;
}

#define CP_ASYNC16(dst, src) \
    asm volatile("cp.async.cg.shared.global [%0], [%1], 16;" :: "r"(dst), "l"(src) : "memory")
#define CP_COMMIT() asm volatile("cp.async.commit_group;" ::: "memory")
template <int N>
__device__ __forceinline__ void cp_wait() {
    asm volatile("cp.async.wait_group %0;" :: "n"(N) : "memory");
}

__device__ __forceinline__ void ldsm4(uint32_t addr, uint32_t& r0, uint32_t& r1,
                                      uint32_t& r2, uint32_t& r3) {
    asm volatile("ldmatrix.sync.aligned.m8n8.x4.shared.b16 {%0,%1,%2,%3}, [%4];"
                 : "=r"(r0), "=r"(r1), "=r"(r2), "=r"(r3) : "r"(addr));
}

__device__ __forceinline__ void mma16816(float* c, uint32_t a0, uint32_t a1,
                                         uint32_t a2, uint32_t a3,
                                         uint32_t b0, uint32_t b1) {
    asm volatile(
        "mma.sync.aligned.m16n8k16.row.col.f32.f16.f16.f32 "
        "{%0,%1,%2,%3}, {%4,%5,%6,%7}, {%8,%9}, {%0,%1,%2,%3};"
        : "+f"(c[0]), "+f"(c[1]), "+f"(c[2]), "+f"(c[3])
        : "r"(a0), "r"(a1), "r"(a2), "r"(a3), "r"(b0), "r"(b1));
}

// blocked-atom SW128 byte offset within a 128x128 fp16 tile (atom = 8 rows x 64 halves)
__device__ __forceinline__ uint32_t tile_off(int row, int col) {
    const uint32_t b = (uint32_t)(((row >> 3) + (col >> 6) * 16) * 1024
                                  + (row & 7) * 128 + (col & 63) * 2);
    return b ^ ((b >> 3) & 0x70);
}

// =================================================================================
// Fused prep kernel: A 2-way fp16 split, B fp16 tiles, proto pack (dtype autodetect).
// =================================================================================
__global__ void __launch_bounds__(256) prep_fused_kernel(const float* __restrict__ feat,
                                                         const float* __restrict__ R,
                                                         const void*  __restrict__ proto_raw)
{
    const int bx = blockIdx.x;

    if (bx < PA_BLOCKS) {
        const int idx = bx * 256 + threadIdx.x;     // 8192*64
        const int b   = idx >> 6;
        const int kp  = idx & 63;
        const int t   = b >> 7, m = b & 127, k = kp * 2;

        const float2 x = *(const float2*)(feat + b * FK + k);

        unsigned w[2];
        {
            float v0 = x.x, v1 = x.y;
            #pragma unroll
            for (int s = 0; s < 2; s++) {
                const __half h0 = __float2half(v0);
                const __half h1 = __float2half(v1);
                w[s] = ((unsigned)__half_as_ushort(h1) << 16) | __half_as_ushort(h0);
                v0 -= __half2float(h0);
                v1 -= __half2float(h1);
            }
        }

        const uint32_t off = tile_off(m, k) >> 2;
        unsigned* base = (unsigned*)g_Abf;
        #pragma unroll
        for (int s = 0; s < 2; s++)
            base[(s * MT + t) * (TILE_U4 * 4) + off] = w[s];
        return;
    }

    if (bx < PA_BLOCKS + PB_BLOCKS) {
        const int idx = (bx - PA_BLOCKS) * 256 + threadIdx.x;   // 64 * NT*128 exactly
        const int kp = idx / (NT * 128);
        const int d  = idx - kp * (NT * 128);
        const int t  = d >> 7, n = d & 127, k = kp * 2;

        float v0 = 0.0f, v1 = 0.0f;
        if (d < DD) {
            v0 = R[k * DD + d];
            v1 = R[(k + 1) * DD + d];
        }
        const __half h0 = __float2half(v0);   // +/-1 exact
        const __half h1 = __float2half(v1);
        const unsigned w = ((unsigned)__half_as_ushort(h1) << 16) | __half_as_ushort(h0);

        ((unsigned*)g_Bbf)[t * (TILE_U4 * 4) + (tile_off(n, k) >> 2)] = w;
        return;
    }

    // ---------------- pack prototypes ----------------
    const int c   = bx - (PA_BLOCKS + PB_BLOCKS);
    const int tid = threadIdx.x;

    __shared__ int s_f32bad, s_i32bad;
    if (tid == 0) { s_f32bad = 0; s_i32bad = 0; }
    __syncthreads();
    {
        const unsigned v = ((const unsigned*)proto_raw)[tid];
        if (v != 0u && v != 0x3F800000u) atomicOr(&s_f32bad, 1);
        if (v > 1u)                      atomicOr(&s_i32bad, 1);
    }
    __syncthreads();
    const int mode = (!s_f32bad) ? 2 : ((!s_i32bad) ? 1 : 0);   // 2=f32, 1=i32, 0=u8

    const unsigned char* p8  = (const unsigned char*)proto_raw;
    const int*           p32 = (const int*)proto_raw;
    const float*         pf  = (const float*)proto_raw;

    int sum = 0;
    for (int w = tid; w < HV_W; w += 256) {
        unsigned word = 0;
        if (w < 313) {
            const int dbase = w * 32;
            #pragma unroll 8
            for (int j = 0; j < 32; j++) {
                const int d = dbase + j;
                if (d < DD) {
                    bool bit;
                    if (mode == 2)      bit = (pf[c * DD + d] != 0.0f);
                    else if (mode == 1) bit = (p32[c * DD + d] != 0);
                    else                bit = (p8[c * DD + d] != 0);
                    if (bit) word |= (1u << j);
                }
            }
        }
        sum += __popc(word);
        ((unsigned*)g_proto)[((w >> 2) * CC + c) * 4 + (w & 3)] = word;
    }

    __shared__ int red[256];
    red[tid] = sum;
    __syncthreads();
    #pragma unroll
    for (int s = 128; s > 0; s >>= 1) {
        if (tid < s) red[tid] += red[tid + s];
        __syncthreads();
    }
    if (tid == 0) g_protopop[c] = red[0];
}

// =================================================================================
// GEMM kernel, n-loop variant: CTA owns m-tile (A both fp16 planes resident, 64 KB)
// and loops over up-to-5 n-tiles with double-buffered B. 512 threads, 16 warps,
// warp-tile 32m x 32n. Per tile: MMA -> pack -> store to g_hv. NO dot fusion.
// smem 130 KB -> 1 CTA/SM.
// =================================================================================
#define SMO_A0   0
#define SMO_A1   32768
#define SMO_B0   65536
#define SMO_B1   98304
#define SMO_WRD  131072        // 2048 B: words [128][4]
#define SM_TOT   133120

__global__ void __launch_bounds__(512, 1) gemm_kernel()
{
    extern __shared__ char sm[];
    const uint32_t smem_base = smem_u32(sm);
    const int tid  = threadIdx.x;
    const int lane = tid & 31, wid = tid >> 5;
    const int grp = blockIdx.x, mt = blockIdx.y;
    const int nt0 = grp * 5;
    const int cnt = (79 - nt0 < 5) ? (79 - nt0) : 5;   // 5 tiles, last group 4

    // ---- prologue async copies: G0 = A0+A1+B0, G1 = B1 ----
    {
        const uint4* srcA0 = g_Abf + (0 * MT + mt) * TILE_U4;
        const uint4* srcA1 = g_Abf + (1 * MT + mt) * TILE_U4;
        const uint4* srcB0 = g_Bbf + (nt0 + 0) * TILE_U4;
        #pragma unroll
        for (int i = 0; i < 4; i++) {
            const int j = tid + i * 512;
            CP_ASYNC16(smem_base + SMO_A0 + j * 16, (const void*)(srcA0 + j));
            CP_ASYNC16(smem_base + SMO_A1 + j * 16, (const void*)(srcA1 + j));
            CP_ASYNC16(smem_base + SMO_B0 + j * 16, (const void*)(srcB0 + j));
        }
        CP_COMMIT();   // G0

        const uint4* srcB1 = g_Bbf + (nt0 + 1) * TILE_U4;
        #pragma unroll
        for (int i = 0; i < 4; i++) {
            const int j = tid + i * 512;
            CP_ASYNC16(smem_base + SMO_B1 + j * 16, (const void*)(srcB1 + j));
        }
        CP_COMMIT();   // G1
    }

    // warp tiles: 16 warps -> (wid&3) m-chunk, (wid>>2) n-chunk
    const int wm = (wid & 3) * 32;
    const int wn = (wid >> 2) * 32;

    uint32_t rbA[2], sxA[2];
    #pragma unroll
    for (int mf = 0; mf < 2; mf++) {
        const int r = wm + mf * 16 + (lane & 15);
        rbA[mf] = (uint32_t)((r >> 3) * 1024 + (r & 7) * 128);
        sxA[mf] = (uint32_t)((r & 7) << 4);
    }
    const uint32_t colselA = (lane & 16) >> 1;   // 0 or 8

    uint32_t rbB[2], sxB[2];
    #pragma unroll
    for (int p = 0; p < 2; p++) {
        const int r = wn + p * 16 + (lane & 7) + ((lane & 16) >> 1);
        rbB[p] = (uint32_t)((r >> 3) * 1024 + (r & 7) * 128);
        sxB[p] = (uint32_t)((r & 7) << 4);
    }
    const uint32_t colselB = lane & 8;

    unsigned* words_s = (unsigned*)(sm + SMO_WRD);   // [128][4]

    for (int j = 0; j < cnt; j++) {
        cp_wait<1>();
        __syncthreads();   // B buf (j&1) ready; words_s from prev tile stored

        float acc[2][4][4];
        #pragma unroll
        for (int mf = 0; mf < 2; mf++)
            #pragma unroll
            for (int nf = 0; nf < 4; nf++)
                #pragma unroll
                for (int i = 0; i < 4; i++) acc[mf][nf][i] = 0.0f;

        const uint32_t bBase = smem_base + ((j & 1) ? SMO_B1 : SMO_B0);

        #pragma unroll
        for (int s = 0; s < 2; s++) {
            const uint32_t aBase = smem_base + (s ? SMO_A1 : SMO_A0);
            #pragma unroll
            for (int kk = 0; kk < 8; kk++) {
                const int k0 = kk * 16;

                uint32_t a[2][4];
                {
                    const int col = k0 + (int)colselA;
                    const uint32_t chi = (col >= 64) ? 16384u : 0u;
                    const uint32_t clo = (uint32_t)((col & 63) << 1);
                    #pragma unroll
                    for (int mf = 0; mf < 2; mf++) {
                        const uint32_t addr = aBase + rbA[mf] + chi + (clo ^ sxA[mf]);
                        ldsm4(addr, a[mf][0], a[mf][1], a[mf][2], a[mf][3]);
                    }
                }

                uint32_t b[4][2];
                {
                    const int col = k0 + (int)colselB;
                    const uint32_t chi = (col >= 64) ? 16384u : 0u;
                    const uint32_t clo = (uint32_t)((col & 63) << 1);
                    #pragma unroll
                    for (int p = 0; p < 2; p++) {
                        const uint32_t addr = bBase + rbB[p] + chi + (clo ^ sxB[p]);
                        uint32_t r0, r1, r2, r3;
                        ldsm4(addr, r0, r1, r2, r3);
                        b[2 * p][0]     = r0;
                        b[2 * p][1]     = r1;
                        b[2 * p + 1][0] = r2;
                        b[2 * p + 1][1] = r3;
                    }
                }

                #pragma unroll
                for (int mf = 0; mf < 2; mf++)
                    #pragma unroll
                    for (int nf = 0; nf < 4; nf++)
                        mma16816(acc[mf][nf], a[mf][0], a[mf][1], a[mf][2], a[mf][3],
                                 b[nf][0], b[nf][1]);
            }
        }

        // ---- refill buf (j&1) for tile j+2 (B of tile j fully consumed) ----
        // issued before pack so the copy overlaps pack+store; commit ALWAYS so
        // the wait<1> depth stays uniform.
        __syncthreads();   // all warps done reading B buf (j&1)
        if (j + 2 < cnt) {
            const int nt2 = nt0 + j + 2;
            const uint32_t bDst = smem_base + ((j & 1) ? SMO_B1 : SMO_B0);
            const uint4* srcB = g_Bbf + nt2 * TILE_U4;
            #pragma unroll
            for (int i = 0; i < 4; i++) {
                const int jj = tid + i * 512;
                CP_ASYNC16(bDst + jj * 16, (const void*)(srcB + jj));
            }
        }
        CP_COMMIT();

        // ---- pack: binarize + shfl-OR; warp covers word column wn>>5, rows wm.. ----
        {
            const int q2 = (lane & 3) * 2;
            const int gg = lane >> 2;
            const int cw = wn >> 5;
            #pragma unroll
            for (int mf = 0; mf < 2; mf++) {
                unsigned lo = 0, hi = 0;
                #pragma unroll
                for (int nf = 0; nf < 4; nf++) {
                    lo |= (acc[mf][nf][0] > 0.0f ? 1u : 0u) << (8 * nf + q2);
                    lo |= (acc[mf][nf][1] > 0.0f ? 1u : 0u) << (8 * nf + q2 + 1);
                    hi |= (acc[mf][nf][2] > 0.0f ? 1u : 0u) << (8 * nf + q2);
                    hi |= (acc[mf][nf][3] > 0.0f ? 1u : 0u) << (8 * nf + q2 + 1);
                }
                lo |= __shfl_xor_sync(0xffffffffu, lo, 1);
                lo |= __shfl_xor_sync(0xffffffffu, lo, 2);
                hi |= __shfl_xor_sync(0xffffffffu, hi, 1);
                hi |= __shfl_xor_sync(0xffffffffu, hi, 2);
                if ((lane & 3) == 0) {
                    words_s[(wm + mf * 16 + gg) * 4 + cw]     = lo;
                    words_s[(wm + mf * 16 + gg + 8) * 4 + cw] = hi;
                }
            }
        }
        __syncthreads();   // pack visible

        if (tid < 128) {
            const uint4 w = *(const uint4*)&words_s[tid * 4];
            *(uint4*)&g_hv[(mt * 128 + tid) * HV_W + (nt0 + j) * 4] = w;
        }
        // next iteration's post-wait __syncthreads orders words_s reuse
    }
}

// =================================================================================
// Stage 3: Hamming similarity via popcount + argmax + output (R7-proven).
// =================================================================================
__global__ void __launch_bounds__(256) hamming_kernel(const float* __restrict__ counts,
                                                      float* __restrict__ out_pred_f,
                                                      int*   __restrict__ out_pred_i,
                                                      float* __restrict__ out_sims)
{
    __shared__ uint4 hv_s[32 * NCH];   // 40 KB
    __shared__ int   rowpop[32];

    const int tid = threadIdx.x;
    const int b0  = blockIdx.x * 32;

    if (tid < 32) rowpop[tid] = 0;
    __syncthreads();

    {
        const int bl = tid >> 3;
        const int j0 = tid & 7;
        const uint4* src = (const uint4*)g_hv + (b0 + bl) * NCH;
        int psum = 0;
        #pragma unroll
        for (int i = 0; i < 10; i++) {
            const int j = j0 + 8 * i;
            uint4 v;
            if (j < 79) v = src[j];
            else        v = make_uint4(0u, 0u, 0u, 0u);
            hv_s[bl * NCH + j] = v;
            psum += __popc(v.x) + __popc(v.y) + __popc(v.z) + __popc(v.w);
        }
        atomicAdd(&rowpop[bl], psum);
    }
    __syncthreads();

    int dot[16];
    const bool active = (tid < 200);
    const int  c  = tid % 100;
    const int  bh = tid / 100;

    if (active) {
        #pragma unroll
        for (int i = 0; i < 16; i++) dot[i] = 0;

        for (int ch = 0; ch < NCH; ch++) {
            const uint4 p = g_proto[ch * CC + c];
            #pragma unroll
            for (int i = 0; i < 16; i++) {
                const uint4 h = hv_s[(bh * 16 + i) * NCH + ch];
                dot[i] += __popc(p.x & h.x) + __popc(p.y & h.y)
                        + __popc(p.z & h.z) + __popc(p.w & h.w);
            }
        }
    }
    __syncthreads();

    float* sims_s = (float*)hv_s;

    if (active) {
        const int   pp  = g_protopop[c];
        const float cnt = counts[c];
        #pragma unroll
        for (int i = 0; i < 16; i++) {
            const int bl  = bh * 16 + i;
            const int ham = rowpop[bl] + pp - 2 * dot[i];
            const float s = (cnt > 0.0f) ? (1.0f - (float)ham / 10000.0f) : 0.0f;
            sims_s[bl * CC + c] = s;
            if (out_sims) out_sims[(b0 + bl) * CC + c] = s;
        }
    }
    __syncthreads();

    if (tid < 32) {
        float best = sims_s[tid * CC];
        int   bidx = 0;
        for (int cc2 = 1; cc2 < CC; cc2++) {
            const float v = sims_s[tid * CC + cc2];
            if (v > best) { best = v; bidx = cc2; }
        }
        if (out_pred_f) out_pred_f[b0 + tid] = (float)bidx;
        if (out_pred_i) out_pred_i[b0 + tid] = bidx;
    }
}

// =================================================================================
// Launch
// =================================================================================
extern "C" void kernel_launch(void* const* d_in, const int* in_sizes, int n_in,
                              void* d_out, int out_size)
{
    const float* feat   = (const float*)d_in[0];
    const float* R      = (const float*)d_in[1];
    const void*  proto  = d_in[2];
    const float* counts = (const float*)d_in[3];

    cudaFuncSetAttribute(gemm_kernel, cudaFuncAttributeMaxDynamicSharedMemorySize, SM_TOT);

    prep_fused_kernel<<<PREP_BLOCKS, 256>>>(feat, R, proto);
    gemm_kernel<<<dim3(NG, MT), 512, SM_TOT>>>();

    float* outf   = (float*)d_out;
    float* pred_f = nullptr;
    int*   pred_i = nullptr;
    float* sims   = nullptr;
    if (out_size >= BN + BN * CC) {
        pred_f = outf;
        sims   = outf + BN;
    } else if (out_size >= BN * CC) {
        sims = outf;
    } else {
        pred_i = (int*)d_out;
    }

    hamming_kernel<<<256, 256>>>(counts, pred_f, pred_i, sims);
}

// round 10
// speedup vs baseline: 1.4626x; 1.1038x over previous
#include <cuda_runtime.h>
#include <cuda_fp16.h>
#include <cstdint>

// Problem constants
#define BN   8192      // batch
#define FK   128       // feature dim (GEMM K)
#define DD   10000     // hypervector dim
#define CC   100       // classes
#define HV_W 320       // padded u32 words per hv row
#define NCH  80        // uint4 chunks per row (hamming)

#define MT   64        // m tiles (8192/128)
#define NT   79        // n tiles (10112 padded / 128)
#define TILE_U4 2048   // uint4 per 128x128 fp16 tile (32 KB)

// fused prep grid partition (widened per-thread work)
#define PA_BLOCKS 512                       // prep_a: 8192 rows x 16 kgroups / 256
#define PB_BLOCKS 632                       // prep_b: 16 kg x 10112 d / 256 (exact)
#define PREP_BLOCKS (PA_BLOCKS + PB_BLOCKS + CC)

// ---------------- scratch (device globals; no allocation allowed) ----------------
__device__ unsigned g_hv[BN * HV_W];            // bitpacked hypervectors (~10.5 MB)
__device__ uint4    g_proto[NCH * CC];          // packed prototypes [chunk][class]
__device__ int      g_protopop[CC];             // per-class popcount
__device__ uint4    g_Abf[2 * MT * TILE_U4];    // feat 2-split fp16 planes (4 MB)
__device__ uint4    g_Bbf[NT * TILE_U4];        // R fp16, tile-image layout (2.6 MB)

// ============================ helpers ==============================
__device__ __forceinline__ uint32_t smem_u32(const void* p) {
    uint32_t a;
    asm("{ .reg .u64 t; cvta.to.shared.u64 t, %1; cvt.u32.u64 %0, t; }" : "=r"(a) : "l"(p));
    return a;
}

#define CP_ASYNC16(dst, src) \
    asm volatile("cp.async.cg.shared.global [%0], [%1], 16;" :: "r"(dst), "l"(src) : "memory")
#define CP_COMMIT() asm volatile("cp.async.commit_group;" ::: "memory")
template <int N>
__device__ __forceinline__ void cp_wait() {
    asm volatile("cp.async.wait_group %0;" :: "n"(N) : "memory");
}

__device__ __forceinline__ void ldsm4(uint32_t addr, uint32_t& r0, uint32_t& r1,
                                      uint32_t& r2, uint32_t& r3) {
    asm volatile("ldmatrix.sync.aligned.m8n8.x4.shared.b16 {%0,%1,%2,%3}, [%4];"
                 : "=r"(r0), "=r"(r1), "=r"(r2), "=r"(r3) : "r"(addr));
}

__device__ __forceinline__ void mma16816(float* c, uint32_t a0, uint32_t a1,
                                         uint32_t a2, uint32_t a3,
                                         uint32_t b0, uint32_t b1) {
    asm volatile(
        "mma.sync.aligned.m16n8k16.row.col.f32.f16.f16.f32 "
        "{%0,%1,%2,%3}, {%4,%5,%6,%7}, {%8,%9}, {%0,%1,%2,%3};"
        : "+f"(c[0]), "+f"(c[1]), "+f"(c[2]), "+f"(c[3])
        : "r"(a0), "r"(a1), "r"(a2), "r"(a3), "r"(b0), "r"(b1));
}

// blocked-atom SW128 byte offset within a 128x128 fp16 tile (atom = 8 rows x 64 halves)
__device__ __forceinline__ uint32_t tile_off(int row, int col) {
    const uint32_t b = (uint32_t)(((row >> 3) + (col >> 6) * 16) * 1024
                                  + (row & 7) * 128 + (col & 63) * 2);
    return b ^ ((b >> 3) & 0x70);
}

__device__ __forceinline__ unsigned pack_pair(float v0, float v1, float& r0, float& r1) {
    const __half h0 = __float2half(v0);
    const __half h1 = __float2half(v1);
    r0 = v0 - __half2float(h0);
    r1 = v1 - __half2float(h1);
    return ((unsigned)__half_as_ushort(h1) << 16) | __half_as_ushort(h0);
}

__device__ __forceinline__ int popc4(uint4 a, uint4 b) {
    return __popc(a.x & b.x) + __popc(a.y & b.y) + __popc(a.z & b.z) + __popc(a.w & b.w);
}

// =================================================================================
// Fused prep kernel: A 2-way fp16 split, B fp16 tiles, proto pack (dtype autodetect).
// Widened per-thread work for MLP (prep is DRAM-latency bound).
// =================================================================================
__global__ void __launch_bounds__(256) prep_fused_kernel(const float* __restrict__ feat,
                                                         const float* __restrict__ R,
                                                         const void*  __restrict__ proto_raw)
{
    const int bx = blockIdx.x;

    if (bx < PA_BLOCKS) {
        // ---- prep A: thread handles one row-m, 8 consecutive k (2x LDG.128) ----
        const int idx = bx * 256 + threadIdx.x;   // 8192 * 16
        const int b   = idx >> 4;
        const int kg  = idx & 15;
        const int t   = b >> 7, m = b & 127, k0 = kg * 8;

        const float4 x0 = *(const float4*)(feat + b * FK + k0);
        const float4 x1 = *(const float4*)(feat + b * FK + k0 + 4);

        float r[8];
        uint4 w0, w1;   // plane 0 / plane 1 words for k0..k0+7
        w0.x = pack_pair(x0.x, x0.y, r[0], r[1]);
        w0.y = pack_pair(x0.z, x0.w, r[2], r[3]);
        w0.z = pack_pair(x1.x, x1.y, r[4], r[5]);
        w0.w = pack_pair(x1.z, x1.w, r[6], r[7]);
        float dummy0, dummy1;
        w1.x = pack_pair(r[0], r[1], dummy0, dummy1);
        w1.y = pack_pair(r[2], r[3], dummy0, dummy1);
        w1.z = pack_pair(r[4], r[5], dummy0, dummy1);
        w1.w = pack_pair(r[6], r[7], dummy0, dummy1);

        // 16B chunk at (m, k0): contiguous+aligned under swizzle (k0 multiple of 8)
        const uint32_t o16 = tile_off(m, k0) >> 4;
        g_Abf[(0 * MT + t) * TILE_U4 + o16] = w0;
        g_Abf[(1 * MT + t) * TILE_U4 + o16] = w1;
        return;
    }

    if (bx < PA_BLOCKS + PB_BLOCKS) {
        // ---- prep B: thread handles one d, 8 consecutive k (8 strided LDG, MLP=8) ----
        const int idx = (bx - PA_BLOCKS) * 256 + threadIdx.x;   // 16 * 10112 exactly
        const int kg = idx / (NT * 128);
        const int d  = idx - kg * (NT * 128);
        const int t  = d >> 7, n = d & 127, k0 = kg * 8;

        float v[8];
        #pragma unroll
        for (int kk = 0; kk < 8; kk++)
            v[kk] = (d < DD) ? R[(k0 + kk) * DD + d] : 0.0f;

        uint4 w;
        {
            float s0, s1;
            w.x = pack_pair(v[0], v[1], s0, s1);
            w.y = pack_pair(v[2], v[3], s0, s1);
            w.z = pack_pair(v[4], v[5], s0, s1);
            w.w = pack_pair(v[6], v[7], s0, s1);
        }
        g_Bbf[t * TILE_U4 + (tile_off(n, k0) >> 4)] = w;
        return;
    }

    // ---------------- pack prototypes ----------------
    const int c   = bx - (PA_BLOCKS + PB_BLOCKS);
    const int tid = threadIdx.x;

    __shared__ int s_f32bad, s_i32bad;
    if (tid == 0) { s_f32bad = 0; s_i32bad = 0; }
    __syncthreads();
    {
        const unsigned v = ((const unsigned*)proto_raw)[tid];
        if (v != 0u && v != 0x3F800000u) atomicOr(&s_f32bad, 1);
        if (v > 1u)                      atomicOr(&s_i32bad, 1);
    }
    __syncthreads();
    const int mode = (!s_f32bad) ? 2 : ((!s_i32bad) ? 1 : 0);   // 2=f32, 1=i32, 0=u8

    const unsigned char* p8  = (const unsigned char*)proto_raw;
    const int*           p32 = (const int*)proto_raw;
    const float*         pf  = (const float*)proto_raw;

    int sum = 0;
    for (int w = tid; w < HV_W; w += 256) {
        unsigned word = 0;
        if (w < 313) {
            const int dbase = w * 32;
            #pragma unroll 8
            for (int j = 0; j < 32; j++) {
                const int d = dbase + j;
                if (d < DD) {
                    bool bit;
                    if (mode == 2)      bit = (pf[c * DD + d] != 0.0f);
                    else if (mode == 1) bit = (p32[c * DD + d] != 0);
                    else                bit = (p8[c * DD + d] != 0);
                    if (bit) word |= (1u << j);
                }
            }
        }
        sum += __popc(word);
        ((unsigned*)g_proto)[((w >> 2) * CC + c) * 4 + (w & 3)] = word;
    }

    __shared__ int red[256];
    red[tid] = sum;
    __syncthreads();
    #pragma unroll
    for (int s = 128; s > 0; s >>= 1) {
        if (tid < s) red[tid] += red[tid + s];
        __syncthreads();
    }
    if (tid == 0) g_protopop[c] = red[0];
}

// =================================================================================
// GEMM kernel (R7-proven, untouched): 128x128 tile per CTA, mma.sync fp16 HMMA,
// 2 fp16 split planes fully prefetched, smem 98.3 KB -> 2 CTAs/SM.
// =================================================================================
#define SMO_A0   0
#define SMO_A1   32768
#define SMO_B    65536
#define SMO_WRD  98304
#define SM_TOT   (SMO_WRD + 2048)

__global__ void __launch_bounds__(256, 2) gemm_kernel()
{
    extern __shared__ char sm[];
    const uint32_t smem_base = smem_u32(sm);
    const int tid  = threadIdx.x;
    const int lane = tid & 31, wid = tid >> 5;
    const int nt = blockIdx.x, mt = blockIdx.y;

    // ---- async copies: g0 = B + A0, g1 = A1 ----
    {
        const uint4* srcB = g_Bbf + nt * TILE_U4;
        #pragma unroll
        for (int i = 0; i < 8; i++) {
            const int j = tid + i * 256;
            CP_ASYNC16(smem_base + SMO_B + j * 16, (const void*)(srcB + j));
        }
        const uint4* srcA0 = g_Abf + (0 * MT + mt) * TILE_U4;
        #pragma unroll
        for (int i = 0; i < 8; i++) {
            const int j = tid + i * 256;
            CP_ASYNC16(smem_base + SMO_A0 + j * 16, (const void*)(srcA0 + j));
        }
        CP_COMMIT();
        const uint4* srcA1 = g_Abf + (1 * MT + mt) * TILE_U4;
        #pragma unroll
        for (int i = 0; i < 8; i++) {
            const int j = tid + i * 256;
            CP_ASYNC16(smem_base + SMO_A1 + j * 16, (const void*)(srcA1 + j));
        }
        CP_COMMIT();
    }

    const int wm = (wid & 3) * 32;
    const int wn = (wid >> 2) * 64;

    uint32_t rbA[2], sxA[2];
    #pragma unroll
    for (int mf = 0; mf < 2; mf++) {
        const int r = wm + mf * 16 + (lane & 15);
        rbA[mf] = (uint32_t)((r >> 3) * 1024 + (r & 7) * 128);
        sxA[mf] = (uint32_t)((r & 7) << 4);
    }
    const uint32_t colselA = (lane & 16) >> 1;   // 0 or 8

    uint32_t rbB[4], sxB[4];
    #pragma unroll
    for (int p = 0; p < 4; p++) {
        const int r = wn + p * 16 + (lane & 7) + ((lane & 16) >> 1);
        rbB[p] = (uint32_t)((r >> 3) * 1024 + (r & 7) * 128);
        sxB[p] = (uint32_t)((r & 7) << 4);
    }
    const uint32_t colselB = lane & 8;

    float acc[2][8][4];
    #pragma unroll
    for (int mf = 0; mf < 2; mf++)
        #pragma unroll
        for (int nf = 0; nf < 8; nf++)
            #pragma unroll
            for (int i = 0; i < 4; i++) acc[mf][nf][i] = 0.0f;

    #pragma unroll
    for (int s = 0; s < 2; s++) {
        if (s == 0) cp_wait<1>();
        else        cp_wait<0>();
        __syncthreads();

        const uint32_t aBase = smem_base + (s ? SMO_A1 : SMO_A0);
        const uint32_t bBase = smem_base + SMO_B;

        #pragma unroll
        for (int kk = 0; kk < 8; kk++) {
            const int k0 = kk * 16;

            uint32_t a[2][4];
            {
                const int col = k0 + (int)colselA;
                const uint32_t chi = (col >= 64) ? 16384u : 0u;
                const uint32_t clo = (uint32_t)((col & 63) << 1);
                #pragma unroll
                for (int mf = 0; mf < 2; mf++) {
                    const uint32_t addr = aBase + rbA[mf] + chi + (clo ^ sxA[mf]);
                    ldsm4(addr, a[mf][0], a[mf][1], a[mf][2], a[mf][3]);
                }
            }

            uint32_t b[8][2];
            {
                const int col = k0 + (int)colselB;
                const uint32_t chi = (col >= 64) ? 16384u : 0u;
                const uint32_t clo = (uint32_t)((col & 63) << 1);
                #pragma unroll
                for (int p = 0; p < 4; p++) {
                    const uint32_t addr = bBase + rbB[p] + chi + (clo ^ sxB[p]);
                    uint32_t r0, r1, r2, r3;
                    ldsm4(addr, r0, r1, r2, r3);
                    b[2 * p][0]     = r0;
                    b[2 * p][1]     = r1;
                    b[2 * p + 1][0] = r2;
                    b[2 * p + 1][1] = r3;
                }
            }

            #pragma unroll
            for (int mf = 0; mf < 2; mf++)
                #pragma unroll
                for (int nf = 0; nf < 8; nf++)
                    mma16816(acc[mf][nf], a[mf][0], a[mf][1], a[mf][2], a[mf][3],
                             b[nf][0], b[nf][1]);
        }
    }

    // ---- epilogue: binarize + pack via shfl-OR, stage words, vector store ----
    unsigned* words_s = (unsigned*)(sm + SMO_WRD);   // [128][4]
    const int q2 = (lane & 3) * 2;
    const int g  = lane >> 2;

    #pragma unroll
    for (int mf = 0; mf < 2; mf++) {
        #pragma unroll
        for (int nc = 0; nc < 2; nc++) {
            unsigned lo = 0, hi = 0;
            #pragma unroll
            for (int f2 = 0; f2 < 4; f2++) {
                const int fi = nc * 4 + f2;
                lo |= (acc[mf][fi][0] > 0.0f ? 1u : 0u) << (8 * f2 + q2);
                lo |= (acc[mf][fi][1] > 0.0f ? 1u : 0u) << (8 * f2 + q2 + 1);
                hi |= (acc[mf][fi][2] > 0.0f ? 1u : 0u) << (8 * f2 + q2);
                hi |= (acc[mf][fi][3] > 0.0f ? 1u : 0u) << (8 * f2 + q2 + 1);
            }
            lo |= __shfl_xor_sync(0xffffffffu, lo, 1);
            lo |= __shfl_xor_sync(0xffffffffu, lo, 2);
            hi |= __shfl_xor_sync(0xffffffffu, hi, 1);
            hi |= __shfl_xor_sync(0xffffffffu, hi, 2);
            if ((lane & 3) == 0) {
                const int cw = (wn >> 5) + nc;
                words_s[(wm + mf * 16 + g) * 4 + cw]     = lo;
                words_s[(wm + mf * 16 + g + 8) * 4 + cw] = hi;
            }
        }
    }
    __syncthreads();

    if (tid < 128) {
        const uint4 w = *(const uint4*)&words_s[tid * 4];
        *(uint4*)&g_hv[(mt * 128 + tid) * HV_W + nt * 4] = w;
    }
}

// =================================================================================
// Stage 3: Hamming + argmax. Re-blocked: thread = (4 rows x 4 classes) -> h-LDS
// amortized 4x (was 16 rows x 1 class). Integer math identical -> exact outputs.
// =================================================================================
__global__ void __launch_bounds__(256) hamming_kernel(const float* __restrict__ counts,
                                                      float* __restrict__ out_pred_f,
                                                      int*   __restrict__ out_pred_i,
                                                      float* __restrict__ out_sims)
{
    __shared__ uint4 hv_s[32 * NCH];   // 40 KB
    __shared__ int   rowpop[32];

    const int tid = threadIdx.x;
    const int b0  = blockIdx.x * 32;

    if (tid < 32) rowpop[tid] = 0;
    __syncthreads();

    {
        const int bl = tid >> 3;
        const int j0 = tid & 7;
        const uint4* src = (const uint4*)g_hv + (b0 + bl) * NCH;
        int psum = 0;
        #pragma unroll
        for (int i = 0; i < 10; i++) {
            const int j = j0 + 8 * i;
            uint4 v;
            if (j < 79) v = src[j];
            else        v = make_uint4(0u, 0u, 0u, 0u);
            hv_s[bl * NCH + j] = v;
            psum += __popc(v.x) + __popc(v.y) + __popc(v.z) + __popc(v.w);
        }
        atomicAdd(&rowpop[bl], psum);
    }
    __syncthreads();

    // thread t < 200: cg = t%25 -> classes 4cg..4cg+3 ; rg = t/25 -> rows 4rg..4rg+3
    const bool active = (tid < 200);
    const int  cg = tid % 25;
    const int  rg = tid / 25;
    const int  c0 = cg * 4;
    const int  r0 = rg * 4;

    int dot[4][4];
    if (active) {
        #pragma unroll
        for (int i = 0; i < 4; i++)
            #pragma unroll
            for (int j = 0; j < 4; j++) dot[i][j] = 0;

        for (int ch = 0; ch < NCH; ch++) {
            uint4 p[4];
            #pragma unroll
            for (int j = 0; j < 4; j++) p[j] = g_proto[ch * CC + c0 + j];
            uint4 h[4];
            #pragma unroll
            for (int i = 0; i < 4; i++) h[i] = hv_s[(r0 + i) * NCH + ch];
            #pragma unroll
            for (int i = 0; i < 4; i++)
                #pragma unroll
                for (int j = 0; j < 4; j++)
                    dot[i][j] += popc4(p[j], h[i]);
        }
    }
    __syncthreads();   // done reading hv_s; safe to reuse as sims buffer

    float* sims_s = (float*)hv_s;   // 32*100 floats = 12.8 KB <= 40 KB

    if (active) {
        #pragma unroll
        for (int j = 0; j < 4; j++) {
            const int   c   = c0 + j;
            const int   pp  = g_protopop[c];
            const float cnt = counts[c];
            #pragma unroll
            for (int i = 0; i < 4; i++) {
                const int bl  = r0 + i;
                const int ham = rowpop[bl] + pp - 2 * dot[i][j];
                const float s = (cnt > 0.0f) ? (1.0f - (float)ham / 10000.0f) : 0.0f;
                sims_s[bl * CC + c] = s;
                if (out_sims) out_sims[(b0 + bl) * CC + c] = s;
            }
        }
    }
    __syncthreads();

    if (tid < 32) {
        float best = sims_s[tid * CC];
        int   bidx = 0;
        for (int cc2 = 1; cc2 < CC; cc2++) {
            const float v = sims_s[tid * CC + cc2];
            if (v > best) { best = v; bidx = cc2; }
        }
        if (out_pred_f) out_pred_f[b0 + tid] = (float)bidx;
        if (out_pred_i) out_pred_i[b0 + tid] = bidx;
    }
}

// =================================================================================
// Launch
// =================================================================================
extern "C" void kernel_launch(void* const* d_in, const int* in_sizes, int n_in,
                              void* d_out, int out_size)
{
    const float* feat   = (const float*)d_in[0];
    const float* R      = (const float*)d_in[1];
    const void*  proto  = d_in[2];
    const float* counts = (const float*)d_in[3];

    cudaFuncSetAttribute(gemm_kernel, cudaFuncAttributeMaxDynamicSharedMemorySize, SM_TOT);

    prep_fused_kernel<<<PREP_BLOCKS, 256>>>(feat, R, proto);
    gemm_kernel<<<dim3(NT, MT), 256, SM_TOT>>>();

    float* outf   = (float*)d_out;
    float* pred_f = nullptr;
    int*   pred_i = nullptr;
    float* sims   = nullptr;
    if (out_size >= BN + BN * CC) {
        pred_f = outf;
        sims   = outf + BN;
    } else if (out_size >= BN * CC) {
        sims = outf;
    } else {
        pred_i = (int*)d_out;
    }

    hamming_kernel<<<256, 256>>>(counts, pred_f, pred_i, sims);
}